// round 15
// baseline (speedup 1.0000x reference)
#include <cuda_runtime.h>
#include <cuda_bf16.h>
#include <cuda_fp16.h>
#include <math.h>
#include <stdint.h>

#define B_    4
#define C_    128
#define N_    8192
#define CQK_  32
#define LOG2E 1.4426950408889634f
#define BIAS2 64.0f

// ------------------- device scratch (__device__ globals) -------------------
__device__ __align__(16) __half        g_q[B_ * N_ * 64];           // (B,N,64) fp16 q (log2e-scaled, pos dims 32-34)
__device__ __align__(16) __half        g_k[B_ * N_ * 64];           // (B,N,64) fp16 k
__device__ __align__(16) __nv_bfloat16 g_v[(size_t)B_ * C_ * N_];   // (B,C,N) v bf16

// ------------------------------ helpers -----------------------------------
__device__ __forceinline__ uint32_t smem_u32(const void* p) {
    uint32_t a;
    asm("{ .reg .u64 t; cvta.to.shared.u64 t, %1; cvt.u32.u64 %0, t; }"
        : "=r"(a) : "l"(p));
    return a;
}
__device__ __forceinline__ float ex2f(float x) {
    float y; asm("ex2.approx.ftz.f32 %0, %1;" : "=f"(y) : "f"(x)); return y;
}
__device__ __forceinline__ uint32_t packbf2(float lo, float hi) {
    __nv_bfloat162 h2 = __floats2bfloat162_rn(lo, hi);
    return *reinterpret_cast<uint32_t*>(&h2);
}

#define LDSM_X4(r0, r1, r2, r3, addr)                                         \
    asm volatile("ldmatrix.sync.aligned.m8n8.x4.shared.b16 {%0,%1,%2,%3}, [%4];" \
                 : "=r"(r0), "=r"(r1), "=r"(r2), "=r"(r3) : "r"(addr))

#define MMA_BF16(d, a0, a1, a2, a3, b0, b1)                                   \
    asm volatile("mma.sync.aligned.m16n8k16.row.col.f32.bf16.bf16.f32 "       \
                 "{%0,%1,%2,%3},{%4,%5,%6,%7},{%8,%9},{%0,%1,%2,%3};"         \
                 : "+f"((d)[0]), "+f"((d)[1]), "+f"((d)[2]), "+f"((d)[3])     \
                 : "r"(a0), "r"(a1), "r"(a2), "r"(a3), "r"(b0), "r"(b1))

#define MMA_F16(d, a0, a1, a2, a3, b0, b1)                                    \
    asm volatile("mma.sync.aligned.m16n8k16.row.col.f32.f16.f16.f32 "         \
                 "{%0,%1,%2,%3},{%4,%5,%6,%7},{%8,%9},{%0,%1,%2,%3};"         \
                 : "+f"((d)[0]), "+f"((d)[1]), "+f"((d)[2]), "+f"((d)[3])     \
                 : "r"(a0), "r"(a1), "r"(a2), "r"(a3), "r"(b0), "r"(b1))

#define CP_ASYNC16(dst, src)                                                  \
    asm volatile("cp.async.cg.shared.global [%0], [%1], 16;"                  \
                 :: "r"(dst), "l"(src))
#define CP_COMMIT()  asm volatile("cp.async.commit_group;" ::: "memory")
#define CP_WAIT1()   asm volatile("cp.async.wait_group 1;"  ::: "memory")
#define CP_WAIT0()   asm volatile("cp.async.wait_group 0;"  ::: "memory")

// ===========================================================================
// Projection kernel: fp16 Q/K (log2e folded into Q; pos bias as K-dims 32-34),
// bf16 V in natural (B,C,N) layout.
// ===========================================================================
__global__ __launch_bounds__(256) void proj_kernel(
    const float* __restrict__ x,  const float* __restrict__ xyz,
    const float* __restrict__ Wq, const float* __restrict__ bq,
    const float* __restrict__ Wk, const float* __restrict__ bk,
    const float* __restrict__ Wv, const float* __restrict__ bv)
{
    __shared__ float xs[32][132];
    __shared__ __half sq[32][64], sk[32][64];

    const int b  = blockIdx.y;
    const int n0 = blockIdx.x * 32;
    const int t  = threadIdx.x;

    const float* xb = x + b * C_ * N_;
    for (int idx = t; idx < C_ * 32; idx += 256) {
        int c = idx >> 5, j = idx & 31;
        xs[j][c] = xb[c * N_ + n0 + j];
    }
    if (t < 32) {
        const float* p = xyz + (b * N_ + n0 + t) * 3;
        float px = p[0], py = p[1], pz = p[2];
        float inv = 1.0f / (sqrtf(px*px + py*py + pz*pz) + 1e-8f);
        float pn[3] = { px*inv, py*inv, pz*inv };
        #pragma unroll
        for (int d = 0; d < 3; d++) {
            sq[t][32+d] = __float2half(LOG2E * 0.1f * pn[d]);
            sk[t][32+d] = __float2half(pn[d]);
        }
        __half z = __float2half(0.f);
        for (int d = 35; d < 64; d++) { sq[t][d] = z; sk[t][d] = z; }
    }
    __syncthreads();

    const int j = t & 31;
    const int g = t >> 5;

    {   // q (o<32) and k (o 32..63), 8 outputs/thread
        float acc[8] = {0,0,0,0,0,0,0,0};
        #pragma unroll 4
        for (int cc = 0; cc < 32; cc++) {
            float4 xv = *reinterpret_cast<const float4*>(&xs[j][cc * 4]);
            #pragma unroll
            for (int i = 0; i < 8; i++) {
                int o = g * 8 + i;
                const float* Wrow = (o < 32) ? (Wq + o * C_) : (Wk + (o - 32) * C_);
                float4 w = *reinterpret_cast<const float4*>(Wrow + cc * 4);
                acc[i] = fmaf(w.x, xv.x, fmaf(w.y, xv.y,
                         fmaf(w.z, xv.z, fmaf(w.w, xv.w, acc[i]))));
            }
        }
        #pragma unroll
        for (int i = 0; i < 8; i++) {
            int o = g * 8 + i;
            if (o < 32) sq[j][o]      = __float2half((acc[i] + bq[o]) * LOG2E);
            else        sk[j][o - 32] = __float2half(acc[i] + bk[o - 32]);
        }
    }
    __syncthreads();

    {   // coalesced copy-out: 32 rows x 8 uint4 per array
        int row = t >> 3, c = t & 7;
        size_t off = ((size_t)(b * N_ + n0 + row)) * 64 + c * 8;
        *(uint4*)(g_q + off) = *(const uint4*)(&sq[row][c * 8]);
        *(uint4*)(g_k + off) = *(const uint4*)(&sk[row][c * 8]);
    }

    {   // v: 16 channels/thread, direct bf16 store (B,C,N)
        float acc[16];
        #pragma unroll
        for (int i = 0; i < 16; i++) acc[i] = 0.f;
        #pragma unroll 2
        for (int cc = 0; cc < 32; cc++) {
            float4 xv = *reinterpret_cast<const float4*>(&xs[j][cc * 4]);
            #pragma unroll
            for (int i = 0; i < 16; i++) {
                const float* Wrow = Wv + (g * 16 + i) * C_;
                float4 w = *reinterpret_cast<const float4*>(Wrow + cc * 4);
                acc[i] = fmaf(w.x, xv.x, fmaf(w.y, xv.y,
                         fmaf(w.z, xv.z, fmaf(w.w, xv.w, acc[i]))));
            }
        }
        #pragma unroll
        for (int i = 0; i < 16; i++) {
            int c = g * 16 + i;
            g_v[((size_t)b * C_ + c) * N_ + n0 + j] =
                __float2bfloat16_rn(acc[i] + bv[c]);
        }
    }
}

// ===========================================================================
// mma.sync flash attention, cross-chunk software pipeline.
// 512 threads (16 warps), 256 queries/CTA, 64-key chunks, 3 SMEM KV buffers.
// Iteration ch: PV(ch) using paCur interleaved per-np with QK(ch+1)+softmax
// producing paNext. paA/paB ping-pong via 2x loop unroll (no copies).
//
// SMEM: Q 256*144=36864 | 3 KV bufs (K 9216 + V 18432 = 27648) = 82944
//   total 119808. Epilogue reuses the KV region.
// ===========================================================================
#define ROWB    144
#define SM_Q    0
#define SM_KV   36864
#define KVBUF   27648
#define OFF_K   0
#define OFF_V   9216
#define SM_TOTAL 119808
#define NCH     (N_ / 64)

__global__ __launch_bounds__(512, 1) void attn_kernel(
    const float* __restrict__ x, const float* __restrict__ gamma,
    float* __restrict__ out)
{
    extern __shared__ __align__(16) char smem[];
    const uint32_t sb = smem_u32(smem);

    const int b   = blockIdx.y;
    const int n0q = blockIdx.x * 256;
    const int t   = threadIdx.x;
    const int w   = t >> 5, l = t & 31;
    const int r8    = l & 7;
    const int half  = (l >> 3) & 1;
    const int quart = l >> 4;

    const __half*        k_b = g_k + (size_t)b * N_ * 64;
    const __nv_bfloat16* v_b = g_v + (size_t)b * C_ * N_;

    // ---- stage Q into padded smem rows ----
    {
        const uint4* q = (const uint4*)(g_q + ((size_t)(b * N_ + n0q)) * 64);
        for (int i = t; i < 2048; i += 512) {
            int row = i >> 3, cs = i & 7;
            *(uint4*)(smem + SM_Q + row * ROWB + cs * 16) = q[i];
        }
    }

    // per-lane ldmatrix address components
    const uint32_t aRow  = (uint32_t)((w * 16 + half * 8 + r8) * ROWB); // A (Q rows)
    const uint32_t bRow  = (uint32_t)((quart * 8 + r8) * ROWB);         // B (K/V rows)
    const uint32_t aCol0 = (uint32_t)(quart * 16);                      // A col bytes
    const uint32_t bCol0 = (uint32_t)(half * 16);                       // B col bytes

    float o[16][4];
    #pragma unroll
    for (int i = 0; i < 16; i++)
        #pragma unroll
        for (int e = 0; e < 4; e++) o[i][e] = 0.f;
    float L0 = 0.f, L1 = 0.f;
    uint32_t paA[16], paB[16];

    // ---- cp.async issue of one 64-key chunk into buffer bb ----
    auto issue = [&](int ch, int bb) {
        const int m0 = ch * 64;
        const uint32_t base = sb + SM_KV + bb * KVBUF;
        const int row = t >> 3, cs = t & 7;
        CP_ASYNC16(base + OFF_K + row * ROWB + cs * 16,
                   k_b + (size_t)(m0 + row) * 64 + cs * 8);
        CP_ASYNC16(base + OFF_V + row * ROWB + cs * 16,
                   v_b + (size_t)row * N_ + m0 + cs * 8);
        CP_ASYNC16(base + OFF_V + (row + 64) * ROWB + cs * 16,
                   v_b + (size_t)(row + 64) * N_ + m0 + cs * 8);
    };

    // QK + softmax for chunk ch into pa[]; accumulates L
    auto qk_softmax = [&](int ch, uint32_t* pa) {
        const uint32_t kb2 = sb + SM_KV + (ch % 3) * KVBUF + OFF_K;
        float rs0 = 0.f, rs1 = 0.f;
        #pragma unroll
        for (int np = 0; np < 4; np++) {
            float sA[4] = {0.f,0.f,0.f,0.f}, sB[4] = {0.f,0.f,0.f,0.f};
            #pragma unroll
            for (int ks = 0; ks < 3; ks++) {
                uint32_t qa0, qa1, qa2, qa3, k0, k1, k2, k3;
                LDSM_X4(qa0, qa1, qa2, qa3, sb + SM_Q + aRow + aCol0 + ks * 32);
                LDSM_X4(k0, k1, k2, k3, kb2 + np * (16 * ROWB) + bRow + bCol0 + ks * 32);
                MMA_F16(sA, qa0, qa1, qa2, qa3, k0, k1);
                MMA_F16(sB, qa0, qa1, qa2, qa3, k2, k3);
            }
            float p0 = ex2f(sA[0]-BIAS2), p1 = ex2f(sA[1]-BIAS2);
            float p2 = ex2f(sA[2]-BIAS2), p3 = ex2f(sA[3]-BIAS2);
            rs0 += p0 + p1; rs1 += p2 + p3;
            pa[np*4+0] = packbf2(p0, p1); pa[np*4+1] = packbf2(p2, p3);
            p0 = ex2f(sB[0]-BIAS2); p1 = ex2f(sB[1]-BIAS2);
            p2 = ex2f(sB[2]-BIAS2); p3 = ex2f(sB[3]-BIAS2);
            rs0 += p0 + p1; rs1 += p2 + p3;
            pa[np*4+2] = packbf2(p0, p1); pa[np*4+3] = packbf2(p2, p3);
        }
        rs0 += __shfl_xor_sync(0xffffffffu, rs0, 1);
        rs0 += __shfl_xor_sync(0xffffffffu, rs0, 2);
        rs1 += __shfl_xor_sync(0xffffffffu, rs1, 1);
        rs1 += __shfl_xor_sync(0xffffffffu, rs1, 2);
        L0 += rs0; L1 += rs1;
    };

    // one pipelined iteration: PV(ch) with paC, QK(ch+1)+softmax into paN
    auto iterstep = [&](int ch, uint32_t* paC, uint32_t* paN, bool doNext) {
        CP_WAIT0();
        __syncthreads();
        if (ch + 2 < NCH) { issue(ch + 2, (ch + 2) % 3); CP_COMMIT(); }
        const uint32_t vbase = sb + SM_KV + (ch % 3) * KVBUF + OFF_V;
        const uint32_t kb2   = sb + SM_KV + ((ch + 1) % 3) * KVBUF + OFF_K;
        float rs0 = 0.f, rs1 = 0.f;
        #pragma unroll
        for (int np = 0; np < 4; np++) {
            if (doNext) {
                float sA[4] = {0.f,0.f,0.f,0.f}, sB[4] = {0.f,0.f,0.f,0.f};
                #pragma unroll
                for (int ks = 0; ks < 3; ks++) {
                    uint32_t qa0, qa1, qa2, qa3, k0, k1, k2, k3;
                    LDSM_X4(qa0, qa1, qa2, qa3, sb + SM_Q + aRow + aCol0 + ks * 32);
                    LDSM_X4(k0, k1, k2, k3, kb2 + np * (16 * ROWB) + bRow + bCol0 + ks * 32);
                    MMA_F16(sA, qa0, qa1, qa2, qa3, k0, k1);
                    MMA_F16(sB, qa0, qa1, qa2, qa3, k2, k3);
                }
                float p0 = ex2f(sA[0]-BIAS2), p1 = ex2f(sA[1]-BIAS2);
                float p2 = ex2f(sA[2]-BIAS2), p3 = ex2f(sA[3]-BIAS2);
                rs0 += p0 + p1; rs1 += p2 + p3;
                paN[np*4+0] = packbf2(p0, p1); paN[np*4+1] = packbf2(p2, p3);
                p0 = ex2f(sB[0]-BIAS2); p1 = ex2f(sB[1]-BIAS2);
                p2 = ex2f(sB[2]-BIAS2); p3 = ex2f(sB[3]-BIAS2);
                rs0 += p0 + p1; rs1 += p2 + p3;
                paN[np*4+2] = packbf2(p0, p1); paN[np*4+3] = packbf2(p2, p3);
            }
            #pragma unroll
            for (int cp = 0; cp < 8; cp++) {
                uint32_t v0, v1, v2, v3;
                LDSM_X4(v0, v1, v2, v3,
                        vbase + cp * (16 * ROWB) + bRow + bCol0 + np * 32);
                MMA_BF16(o[2*cp],     paC[np*4+0], paC[np*4+1], paC[np*4+2], paC[np*4+3], v0, v1);
                MMA_BF16(o[2*cp + 1], paC[np*4+0], paC[np*4+1], paC[np*4+2], paC[np*4+3], v2, v3);
            }
        }
        if (doNext) {
            rs0 += __shfl_xor_sync(0xffffffffu, rs0, 1);
            rs0 += __shfl_xor_sync(0xffffffffu, rs0, 2);
            rs1 += __shfl_xor_sync(0xffffffffu, rs1, 1);
            rs1 += __shfl_xor_sync(0xffffffffu, rs1, 2);
            L0 += rs0; L1 += rs1;
        }
    };

    // ---- prologue: chunks 0 and 1 in flight; softmax(0) -> paA ----
    issue(0, 0); CP_COMMIT();
    issue(1, 1); CP_COMMIT();
    CP_WAIT1();                 // chunk 0 resident (chunk 1 may be in flight)
    __syncthreads();
    qk_softmax(0, paA);

    // ---- main pipelined loop (even chunk -> paA current, odd -> paB) ----
    for (int ch = 0; ch < NCH; ch += 2) {
        iterstep(ch,     paA, paB, true);
        iterstep(ch + 1, paB, paA, ch + 2 < NCH);
    }

    // ---- epilogue: out = gamma * O / L + x  (per-warp smem transpose) ----
    const float gm  = __ldg(gamma);
    const float sc0 = gm / L0;
    const float sc1 = gm / L1;
    const int   g   = l >> 2, t4 = l & 3;

    float* buf = (float*)(smem + SM_KV);   // [256][9] floats, KV region dead
    #pragma unroll 1
    for (int ct = 0; ct < 16; ct++) {
        __syncthreads();
        {
            int q0 = w * 16 + g;
            buf[q0 * 9 + 2*t4]           = o[ct][0] * sc0;
            buf[q0 * 9 + 2*t4 + 1]       = o[ct][1] * sc0;
            buf[(q0 + 8) * 9 + 2*t4]     = o[ct][2] * sc1;
            buf[(q0 + 8) * 9 + 2*t4 + 1] = o[ct][3] * sc1;
        }
        __syncthreads();
        for (int i = t; i < 2048; i += 512) {
            int cl = i >> 8, q = i & 255;
            int c  = ct * 8 + cl;
            size_t go = ((size_t)b * C_ + c) * N_ + n0q + q;
            out[go] = buf[q * 9 + cl] + x[go];
        }
    }
}

// ===========================================================================
extern "C" void kernel_launch(void* const* d_in, const int* in_sizes, int n_in,
                              void* d_out, int out_size)
{
    (void)in_sizes; (void)n_in; (void)out_size;
    const float* x     = (const float*)d_in[0];
    const float* xyz   = (const float*)d_in[1];
    const float* Wq    = (const float*)d_in[2];
    const float* bq    = (const float*)d_in[3];
    const float* Wk    = (const float*)d_in[4];
    const float* bk    = (const float*)d_in[5];
    const float* Wv    = (const float*)d_in[6];
    const float* bv    = (const float*)d_in[7];
    const float* gamma = (const float*)d_in[8];
    float* out = (float*)d_out;

    cudaFuncSetAttribute(attn_kernel,
                         cudaFuncAttributeMaxDynamicSharedMemorySize, SM_TOTAL);

    dim3 pg(N_ / 32, B_);
    proj_kernel<<<pg, 256>>>(x, xyz, Wq, bq, Wk, bk, Wv, bv);

    dim3 ag(N_ / 256, B_);
    attn_kernel<<<ag, 512, SM_TOTAL>>>(x, gamma, out);
}

// round 16
// speedup vs baseline: 1.0937x; 1.0937x over previous
#include <cuda_runtime.h>
#include <cuda_bf16.h>
#include <cuda_fp16.h>
#include <math.h>
#include <stdint.h>

#define B_    4
#define C_    128
#define N_    8192
#define CQK_  32
#define LOG2E 1.4426950408889634f
#define BIAS2 64.0f

// ------------------- device scratch (__device__ globals) -------------------
__device__ __align__(16) __half        g_q[B_ * N_ * 64];           // (B,N,64) fp16 q (log2e-scaled, pos dims 32-34)
__device__ __align__(16) __half        g_k[B_ * N_ * 64];           // (B,N,64) fp16 k
__device__ __align__(16) __nv_bfloat16 g_v[(size_t)B_ * C_ * N_];   // (B,C,N) v bf16

// ------------------------------ helpers -----------------------------------
__device__ __forceinline__ uint32_t smem_u32(const void* p) {
    uint32_t a;
    asm("{ .reg .u64 t; cvta.to.shared.u64 t, %1; cvt.u32.u64 %0, t; }"
        : "=r"(a) : "l"(p));
    return a;
}
__device__ __forceinline__ float ex2f(float x) {
    float y; asm("ex2.approx.ftz.f32 %0, %1;" : "=f"(y) : "f"(x)); return y;
}
__device__ __forceinline__ uint32_t packbf2(float lo, float hi) {
    __nv_bfloat162 h2 = __floats2bfloat162_rn(lo, hi);
    return *reinterpret_cast<uint32_t*>(&h2);
}

#define LDSM_X4(r0, r1, r2, r3, addr)                                         \
    asm volatile("ldmatrix.sync.aligned.m8n8.x4.shared.b16 {%0,%1,%2,%3}, [%4];" \
                 : "=r"(r0), "=r"(r1), "=r"(r2), "=r"(r3) : "r"(addr))

#define MMA_BF16(d, a0, a1, a2, a3, b0, b1)                                   \
    asm volatile("mma.sync.aligned.m16n8k16.row.col.f32.bf16.bf16.f32 "       \
                 "{%0,%1,%2,%3},{%4,%5,%6,%7},{%8,%9},{%0,%1,%2,%3};"         \
                 : "+f"((d)[0]), "+f"((d)[1]), "+f"((d)[2]), "+f"((d)[3])     \
                 : "r"(a0), "r"(a1), "r"(a2), "r"(a3), "r"(b0), "r"(b1))

#define MMA_F16(d, a0, a1, a2, a3, b0, b1)                                    \
    asm volatile("mma.sync.aligned.m16n8k16.row.col.f32.f16.f16.f32 "         \
                 "{%0,%1,%2,%3},{%4,%5,%6,%7},{%8,%9},{%0,%1,%2,%3};"         \
                 : "+f"((d)[0]), "+f"((d)[1]), "+f"((d)[2]), "+f"((d)[3])     \
                 : "r"(a0), "r"(a1), "r"(a2), "r"(a3), "r"(b0), "r"(b1))

#define CP_ASYNC16(dst, src)                                                  \
    asm volatile("cp.async.cg.shared.global [%0], [%1], 16;"                  \
                 :: "r"(dst), "l"(src))
#define CP_COMMIT()  asm volatile("cp.async.commit_group;" ::: "memory")
#define CP_WAIT1()   asm volatile("cp.async.wait_group 1;"  ::: "memory")
#define CP_WAIT0()   asm volatile("cp.async.wait_group 0;"  ::: "memory")

// ===========================================================================
// Projection kernel: fp16 Q/K (log2e folded into Q; pos bias as K-dims 32-34),
// bf16 V in natural (B,C,N) layout.
// ===========================================================================
__global__ __launch_bounds__(256) void proj_kernel(
    const float* __restrict__ x,  const float* __restrict__ xyz,
    const float* __restrict__ Wq, const float* __restrict__ bq,
    const float* __restrict__ Wk, const float* __restrict__ bk,
    const float* __restrict__ Wv, const float* __restrict__ bv)
{
    __shared__ float xs[32][132];
    __shared__ __half sq[32][64], sk[32][64];

    const int b  = blockIdx.y;
    const int n0 = blockIdx.x * 32;
    const int t  = threadIdx.x;

    const float* xb = x + b * C_ * N_;
    for (int idx = t; idx < C_ * 32; idx += 256) {
        int c = idx >> 5, j = idx & 31;
        xs[j][c] = xb[c * N_ + n0 + j];
    }
    if (t < 32) {
        const float* p = xyz + (b * N_ + n0 + t) * 3;
        float px = p[0], py = p[1], pz = p[2];
        float inv = 1.0f / (sqrtf(px*px + py*py + pz*pz) + 1e-8f);
        float pn[3] = { px*inv, py*inv, pz*inv };
        #pragma unroll
        for (int d = 0; d < 3; d++) {
            sq[t][32+d] = __float2half(LOG2E * 0.1f * pn[d]);
            sk[t][32+d] = __float2half(pn[d]);
        }
        __half z = __float2half(0.f);
        for (int d = 35; d < 64; d++) { sq[t][d] = z; sk[t][d] = z; }
    }
    __syncthreads();

    const int j = t & 31;
    const int g = t >> 5;

    {   // q (o<32) and k (o 32..63), 8 outputs/thread
        float acc[8] = {0,0,0,0,0,0,0,0};
        #pragma unroll 4
        for (int cc = 0; cc < 32; cc++) {
            float4 xv = *reinterpret_cast<const float4*>(&xs[j][cc * 4]);
            #pragma unroll
            for (int i = 0; i < 8; i++) {
                int o = g * 8 + i;
                const float* Wrow = (o < 32) ? (Wq + o * C_) : (Wk + (o - 32) * C_);
                float4 w = *reinterpret_cast<const float4*>(Wrow + cc * 4);
                acc[i] = fmaf(w.x, xv.x, fmaf(w.y, xv.y,
                         fmaf(w.z, xv.z, fmaf(w.w, xv.w, acc[i]))));
            }
        }
        #pragma unroll
        for (int i = 0; i < 8; i++) {
            int o = g * 8 + i;
            if (o < 32) sq[j][o]      = __float2half((acc[i] + bq[o]) * LOG2E);
            else        sk[j][o - 32] = __float2half(acc[i] + bk[o - 32]);
        }
    }
    __syncthreads();

    {   // coalesced copy-out: 32 rows x 8 uint4 per array
        int row = t >> 3, c = t & 7;
        size_t off = ((size_t)(b * N_ + n0 + row)) * 64 + c * 8;
        *(uint4*)(g_q + off) = *(const uint4*)(&sq[row][c * 8]);
        *(uint4*)(g_k + off) = *(const uint4*)(&sk[row][c * 8]);
    }

    {   // v: 16 channels/thread, direct bf16 store (B,C,N)
        float acc[16];
        #pragma unroll
        for (int i = 0; i < 16; i++) acc[i] = 0.f;
        #pragma unroll 2
        for (int cc = 0; cc < 32; cc++) {
            float4 xv = *reinterpret_cast<const float4*>(&xs[j][cc * 4]);
            #pragma unroll
            for (int i = 0; i < 16; i++) {
                const float* Wrow = Wv + (g * 16 + i) * C_;
                float4 w = *reinterpret_cast<const float4*>(Wrow + cc * 4);
                acc[i] = fmaf(w.x, xv.x, fmaf(w.y, xv.y,
                         fmaf(w.z, xv.z, fmaf(w.w, xv.w, acc[i]))));
            }
        }
        #pragma unroll
        for (int i = 0; i < 16; i++) {
            int c = g * 16 + i;
            g_v[((size_t)b * C_ + c) * N_ + n0 + j] =
                __float2bfloat16_rn(acc[i] + bv[c]);
        }
    }
}

// ===========================================================================
// mma.sync flash attention, cross-chunk software pipeline (macro form so the
// P ping-pong arrays stay register-resident: NO pointer-passed arrays).
// 512 threads (16 warps), 256 queries/CTA, 64-key chunks, 3 SMEM KV buffers.
// Iteration ch: PV(ch) using PAC interleaved per-np with QK(ch+1)+softmax
// producing PAN. paA/paB ping-pong via 2x-unrolled loop.
//
// SMEM: Q 256*144=36864 | 3 KV bufs (K 9216 + V 18432 = 27648) = 82944
//   total 119808. Epilogue reuses the KV region.
// ===========================================================================
#define ROWB    144
#define SM_Q    0
#define SM_KV   36864
#define KVBUF   27648
#define OFF_K   0
#define OFF_V   9216
#define SM_TOTAL 119808
#define NCH     (N_ / 64)

// -- QK(CH) + fixed-bias softmax into PA (16 regs); accumulates L0/L1 --
#define QK_SOFTMAX(CH, PA) do {                                               \
    const uint32_t kb2_ = sb + SM_KV + ((CH) % 3) * KVBUF + OFF_K;            \
    float rs0_ = 0.f, rs1_ = 0.f;                                             \
    _Pragma("unroll")                                                         \
    for (int np = 0; np < 4; np++) {                                          \
        float sA_[4] = {0.f,0.f,0.f,0.f}, sB_[4] = {0.f,0.f,0.f,0.f};         \
        _Pragma("unroll")                                                     \
        for (int ks = 0; ks < 3; ks++) {                                      \
            uint32_t qa0, qa1, qa2, qa3, k0, k1, k2, k3;                      \
            LDSM_X4(qa0, qa1, qa2, qa3, sb + SM_Q + aRow + aCol0 + ks * 32);  \
            LDSM_X4(k0, k1, k2, k3,                                           \
                    kb2_ + np * (16 * ROWB) + bRow + bCol0 + ks * 32);        \
            MMA_F16(sA_, qa0, qa1, qa2, qa3, k0, k1);                         \
            MMA_F16(sB_, qa0, qa1, qa2, qa3, k2, k3);                         \
        }                                                                     \
        float p0 = ex2f(sA_[0]-BIAS2), p1 = ex2f(sA_[1]-BIAS2);               \
        float p2 = ex2f(sA_[2]-BIAS2), p3 = ex2f(sA_[3]-BIAS2);               \
        rs0_ += p0 + p1; rs1_ += p2 + p3;                                     \
        PA[np*4+0] = packbf2(p0, p1); PA[np*4+1] = packbf2(p2, p3);           \
        p0 = ex2f(sB_[0]-BIAS2); p1 = ex2f(sB_[1]-BIAS2);                     \
        p2 = ex2f(sB_[2]-BIAS2); p3 = ex2f(sB_[3]-BIAS2);                     \
        rs0_ += p0 + p1; rs1_ += p2 + p3;                                     \
        PA[np*4+2] = packbf2(p0, p1); PA[np*4+3] = packbf2(p2, p3);           \
    }                                                                         \
    rs0_ += __shfl_xor_sync(0xffffffffu, rs0_, 1);                            \
    rs0_ += __shfl_xor_sync(0xffffffffu, rs0_, 2);                            \
    rs1_ += __shfl_xor_sync(0xffffffffu, rs1_, 1);                            \
    rs1_ += __shfl_xor_sync(0xffffffffu, rs1_, 2);                            \
    L0 += rs0_; L1 += rs1_;                                                   \
} while (0)

// -- one pipelined iteration: PV(CH) with PAC; QK(CH+1)+softmax into PAN --
#define ITERSTEP(CH, PAC, PAN, DONEXT) do {                                   \
    CP_WAIT0();                                                               \
    __syncthreads();                                                          \
    if ((CH) + 2 < NCH) { issue((CH) + 2, ((CH) + 2) % 3); CP_COMMIT(); }     \
    const uint32_t vb_ = sb + SM_KV + ((CH) % 3) * KVBUF + OFF_V;             \
    const uint32_t kb2_ = sb + SM_KV + (((CH) + 1) % 3) * KVBUF + OFF_K;      \
    float rs0_ = 0.f, rs1_ = 0.f;                                             \
    _Pragma("unroll")                                                         \
    for (int np = 0; np < 4; np++) {                                          \
        if (DONEXT) {                                                         \
            float sA_[4] = {0.f,0.f,0.f,0.f}, sB_[4] = {0.f,0.f,0.f,0.f};     \
            _Pragma("unroll")                                                 \
            for (int ks = 0; ks < 3; ks++) {                                  \
                uint32_t qa0, qa1, qa2, qa3, k0, k1, k2, k3;                  \
                LDSM_X4(qa0, qa1, qa2, qa3,                                   \
                        sb + SM_Q + aRow + aCol0 + ks * 32);                  \
                LDSM_X4(k0, k1, k2, k3,                                       \
                        kb2_ + np * (16 * ROWB) + bRow + bCol0 + ks * 32);    \
                MMA_F16(sA_, qa0, qa1, qa2, qa3, k0, k1);                     \
                MMA_F16(sB_, qa0, qa1, qa2, qa3, k2, k3);                     \
            }                                                                 \
            float p0 = ex2f(sA_[0]-BIAS2), p1 = ex2f(sA_[1]-BIAS2);           \
            float p2 = ex2f(sA_[2]-BIAS2), p3 = ex2f(sA_[3]-BIAS2);           \
            rs0_ += p0 + p1; rs1_ += p2 + p3;                                 \
            PAN[np*4+0] = packbf2(p0, p1); PAN[np*4+1] = packbf2(p2, p3);     \
            p0 = ex2f(sB_[0]-BIAS2); p1 = ex2f(sB_[1]-BIAS2);                 \
            p2 = ex2f(sB_[2]-BIAS2); p3 = ex2f(sB_[3]-BIAS2);                 \
            rs0_ += p0 + p1; rs1_ += p2 + p3;                                 \
            PAN[np*4+2] = packbf2(p0, p1); PAN[np*4+3] = packbf2(p2, p3);     \
        }                                                                     \
        _Pragma("unroll")                                                     \
        for (int cp = 0; cp < 8; cp++) {                                      \
            uint32_t v0, v1, v2, v3;                                          \
            LDSM_X4(v0, v1, v2, v3,                                           \
                    vb_ + cp * (16 * ROWB) + bRow + bCol0 + np * 32);         \
            MMA_BF16(o[2*cp],                                                 \
                     PAC[np*4+0], PAC[np*4+1], PAC[np*4+2], PAC[np*4+3],      \
                     v0, v1);                                                 \
            MMA_BF16(o[2*cp + 1],                                             \
                     PAC[np*4+0], PAC[np*4+1], PAC[np*4+2], PAC[np*4+3],      \
                     v2, v3);                                                 \
        }                                                                     \
    }                                                                         \
    if (DONEXT) {                                                             \
        rs0_ += __shfl_xor_sync(0xffffffffu, rs0_, 1);                        \
        rs0_ += __shfl_xor_sync(0xffffffffu, rs0_, 2);                        \
        rs1_ += __shfl_xor_sync(0xffffffffu, rs1_, 1);                        \
        rs1_ += __shfl_xor_sync(0xffffffffu, rs1_, 2);                        \
        L0 += rs0_; L1 += rs1_;                                               \
    }                                                                         \
} while (0)

__global__ __launch_bounds__(512, 1) void attn_kernel(
    const float* __restrict__ x, const float* __restrict__ gamma,
    float* __restrict__ out)
{
    extern __shared__ __align__(16) char smem[];
    const uint32_t sb = smem_u32(smem);

    const int b   = blockIdx.y;
    const int n0q = blockIdx.x * 256;
    const int t   = threadIdx.x;
    const int w   = t >> 5, l = t & 31;
    const int r8    = l & 7;
    const int half  = (l >> 3) & 1;
    const int quart = l >> 4;

    const __half*        k_b = g_k + (size_t)b * N_ * 64;
    const __nv_bfloat16* v_b = g_v + (size_t)b * C_ * N_;

    // ---- stage Q into padded smem rows ----
    {
        const uint4* q = (const uint4*)(g_q + ((size_t)(b * N_ + n0q)) * 64);
        for (int i = t; i < 2048; i += 512) {
            int row = i >> 3, cs = i & 7;
            *(uint4*)(smem + SM_Q + row * ROWB + cs * 16) = q[i];
        }
    }

    // per-lane ldmatrix address components
    const uint32_t aRow  = (uint32_t)((w * 16 + half * 8 + r8) * ROWB); // A (Q rows)
    const uint32_t bRow  = (uint32_t)((quart * 8 + r8) * ROWB);         // B (K/V rows)
    const uint32_t aCol0 = (uint32_t)(quart * 16);                      // A col bytes
    const uint32_t bCol0 = (uint32_t)(half * 16);                       // B col bytes

    float o[16][4];
    #pragma unroll
    for (int i = 0; i < 16; i++)
        #pragma unroll
        for (int e = 0; e < 4; e++) o[i][e] = 0.f;
    float L0 = 0.f, L1 = 0.f;
    uint32_t paA[16], paB[16];

    // ---- cp.async issue of one 64-key chunk into buffer bb ----
    auto issue = [&](int ch, int bb) {
        const int m0 = ch * 64;
        const uint32_t base = sb + SM_KV + bb * KVBUF;
        const int row = t >> 3, cs = t & 7;
        CP_ASYNC16(base + OFF_K + row * ROWB + cs * 16,
                   k_b + (size_t)(m0 + row) * 64 + cs * 8);
        CP_ASYNC16(base + OFF_V + row * ROWB + cs * 16,
                   v_b + (size_t)row * N_ + m0 + cs * 8);
        CP_ASYNC16(base + OFF_V + (row + 64) * ROWB + cs * 16,
                   v_b + (size_t)(row + 64) * N_ + m0 + cs * 8);
    };

    // ---- prologue: chunks 0 and 1 in flight; softmax(0) -> paA ----
    issue(0, 0); CP_COMMIT();
    issue(1, 1); CP_COMMIT();
    CP_WAIT1();                 // chunk 0 resident (chunk 1 may be in flight)
    __syncthreads();
    QK_SOFTMAX(0, paA);

    // ---- main pipelined loop (even chunk -> paA current, odd -> paB) ----
    for (int ch = 0; ch < NCH; ch += 2) {
        ITERSTEP(ch,     paA, paB, true);
        ITERSTEP(ch + 1, paB, paA, (ch + 2 < NCH));
    }

    // ---- epilogue: out = gamma * O / L + x  (per-warp smem transpose) ----
    const float gm  = __ldg(gamma);
    const float sc0 = gm / L0;
    const float sc1 = gm / L1;
    const int   g   = l >> 2, t4 = l & 3;

    float* buf = (float*)(smem + SM_KV);   // [256][9] floats, KV region dead
    #pragma unroll 1
    for (int ct = 0; ct < 16; ct++) {
        __syncthreads();
        {
            int q0 = w * 16 + g;
            buf[q0 * 9 + 2*t4]           = o[ct][0] * sc0;
            buf[q0 * 9 + 2*t4 + 1]       = o[ct][1] * sc0;
            buf[(q0 + 8) * 9 + 2*t4]     = o[ct][2] * sc1;
            buf[(q0 + 8) * 9 + 2*t4 + 1] = o[ct][3] * sc1;
        }
        __syncthreads();
        for (int i = t; i < 2048; i += 512) {
            int cl = i >> 8, q = i & 255;
            int c  = ct * 8 + cl;
            size_t go = ((size_t)b * C_ + c) * N_ + n0q + q;
            out[go] = buf[q * 9 + cl] + x[go];
        }
    }
}

// ===========================================================================
extern "C" void kernel_launch(void* const* d_in, const int* in_sizes, int n_in,
                              void* d_out, int out_size)
{
    (void)in_sizes; (void)n_in; (void)out_size;
    const float* x     = (const float*)d_in[0];
    const float* xyz   = (const float*)d_in[1];
    const float* Wq    = (const float*)d_in[2];
    const float* bq    = (const float*)d_in[3];
    const float* Wk    = (const float*)d_in[4];
    const float* bk    = (const float*)d_in[5];
    const float* Wv    = (const float*)d_in[6];
    const float* bv    = (const float*)d_in[7];
    const float* gamma = (const float*)d_in[8];
    float* out = (float*)d_out;

    cudaFuncSetAttribute(attn_kernel,
                         cudaFuncAttributeMaxDynamicSharedMemorySize, SM_TOTAL);

    dim3 pg(N_ / 32, B_);
    proj_kernel<<<pg, 256>>>(x, xyz, Wq, bq, Wk, bk, Wv, bv);

    dim3 ag(N_ / 256, B_);
    attn_kernel<<<ag, 512, SM_TOTAL>>>(x, gamma, out);
}

// round 17
// speedup vs baseline: 2.4960x; 2.2822x over previous
#include <cuda_runtime.h>
#include <cuda_bf16.h>
#include <cuda_fp16.h>
#include <math.h>
#include <stdint.h>

#define B_    4
#define C_    128
#define N_    8192
#define CQK_  32
#define LOG2E 1.4426950408889634f
#define BIAS2 64.0f

// ------------------- device scratch (__device__ globals) -------------------
__device__ __align__(16) __half        g_q[B_ * N_ * 64];           // (B,N,64) fp16 q (log2e-scaled, pos dims 32-34)
__device__ __align__(16) __half        g_k[B_ * N_ * 64];           // (B,N,64) fp16 k
__device__ __align__(16) __nv_bfloat16 g_v[(size_t)B_ * C_ * N_];   // (B,C,N) v bf16

// ------------------------------ helpers -----------------------------------
__device__ __forceinline__ uint32_t smem_u32(const void* p) {
    uint32_t a;
    asm("{ .reg .u64 t; cvta.to.shared.u64 t, %1; cvt.u32.u64 %0, t; }"
        : "=r"(a) : "l"(p));
    return a;
}
__device__ __forceinline__ float ex2f(float x) {
    float y; asm("ex2.approx.ftz.f32 %0, %1;" : "=f"(y) : "f"(x)); return y;
}
__device__ __forceinline__ uint32_t packbf2(float lo, float hi) {
    __nv_bfloat162 h2 = __floats2bfloat162_rn(lo, hi);
    return *reinterpret_cast<uint32_t*>(&h2);
}

#define LDSM_X4(r0, r1, r2, r3, addr)                                         \
    asm volatile("ldmatrix.sync.aligned.m8n8.x4.shared.b16 {%0,%1,%2,%3}, [%4];" \
                 : "=r"(r0), "=r"(r1), "=r"(r2), "=r"(r3) : "r"(addr))

#define MMA_BF16(d, a0, a1, a2, a3, b0, b1)                                   \
    asm volatile("mma.sync.aligned.m16n8k16.row.col.f32.bf16.bf16.f32 "       \
                 "{%0,%1,%2,%3},{%4,%5,%6,%7},{%8,%9},{%0,%1,%2,%3};"         \
                 : "+f"((d)[0]), "+f"((d)[1]), "+f"((d)[2]), "+f"((d)[3])     \
                 : "r"(a0), "r"(a1), "r"(a2), "r"(a3), "r"(b0), "r"(b1))

#define MMA_F16(d, a0, a1, a2, a3, b0, b1)                                    \
    asm volatile("mma.sync.aligned.m16n8k16.row.col.f32.f16.f16.f32 "         \
                 "{%0,%1,%2,%3},{%4,%5,%6,%7},{%8,%9},{%0,%1,%2,%3};"         \
                 : "+f"((d)[0]), "+f"((d)[1]), "+f"((d)[2]), "+f"((d)[3])     \
                 : "r"(a0), "r"(a1), "r"(a2), "r"(a3), "r"(b0), "r"(b1))

#define CP_ASYNC16(dst, src)                                                  \
    asm volatile("cp.async.cg.shared.global [%0], [%1], 16;"                  \
                 :: "r"(dst), "l"(src))
#define CP_COMMIT()  asm volatile("cp.async.commit_group;" ::: "memory")
#define CP_WAIT1()   asm volatile("cp.async.wait_group 1;"  ::: "memory")
#define CP_WAIT0()   asm volatile("cp.async.wait_group 0;"  ::: "memory")

// ===========================================================================
// Projection kernel: fp16 Q/K (log2e folded into Q; pos bias as K-dims 32-34),
// bf16 V in natural (B,C,N) layout.
// ===========================================================================
__global__ __launch_bounds__(256) void proj_kernel(
    const float* __restrict__ x,  const float* __restrict__ xyz,
    const float* __restrict__ Wq, const float* __restrict__ bq,
    const float* __restrict__ Wk, const float* __restrict__ bk,
    const float* __restrict__ Wv, const float* __restrict__ bv)
{
    __shared__ float xs[32][132];
    __shared__ __half sq[32][64], sk[32][64];

    const int b  = blockIdx.y;
    const int n0 = blockIdx.x * 32;
    const int t  = threadIdx.x;

    const float* xb = x + b * C_ * N_;
    for (int idx = t; idx < C_ * 32; idx += 256) {
        int c = idx >> 5, j = idx & 31;
        xs[j][c] = xb[c * N_ + n0 + j];
    }
    if (t < 32) {
        const float* p = xyz + (b * N_ + n0 + t) * 3;
        float px = p[0], py = p[1], pz = p[2];
        float inv = 1.0f / (sqrtf(px*px + py*py + pz*pz) + 1e-8f);
        float pn[3] = { px*inv, py*inv, pz*inv };
        #pragma unroll
        for (int d = 0; d < 3; d++) {
            sq[t][32+d] = __float2half(LOG2E * 0.1f * pn[d]);
            sk[t][32+d] = __float2half(pn[d]);
        }
        __half z = __float2half(0.f);
        for (int d = 35; d < 64; d++) { sq[t][d] = z; sk[t][d] = z; }
    }
    __syncthreads();

    const int j = t & 31;
    const int g = t >> 5;

    {   // q (o<32) and k (o 32..63), 8 outputs/thread
        float acc[8] = {0,0,0,0,0,0,0,0};
        #pragma unroll 4
        for (int cc = 0; cc < 32; cc++) {
            float4 xv = *reinterpret_cast<const float4*>(&xs[j][cc * 4]);
            #pragma unroll
            for (int i = 0; i < 8; i++) {
                int o = g * 8 + i;
                const float* Wrow = (o < 32) ? (Wq + o * C_) : (Wk + (o - 32) * C_);
                float4 w = *reinterpret_cast<const float4*>(Wrow + cc * 4);
                acc[i] = fmaf(w.x, xv.x, fmaf(w.y, xv.y,
                         fmaf(w.z, xv.z, fmaf(w.w, xv.w, acc[i]))));
            }
        }
        #pragma unroll
        for (int i = 0; i < 8; i++) {
            int o = g * 8 + i;
            if (o < 32) sq[j][o]      = __float2half((acc[i] + bq[o]) * LOG2E);
            else        sk[j][o - 32] = __float2half(acc[i] + bk[o - 32]);
        }
    }
    __syncthreads();

    {   // coalesced copy-out: 32 rows x 8 uint4 per array
        int row = t >> 3, c = t & 7;
        size_t off = ((size_t)(b * N_ + n0 + row)) * 64 + c * 8;
        *(uint4*)(g_q + off) = *(const uint4*)(&sq[row][c * 8]);
        *(uint4*)(g_k + off) = *(const uint4*)(&sk[row][c * 8]);
    }

    {   // v: 16 channels/thread, direct bf16 store (B,C,N)
        float acc[16];
        #pragma unroll
        for (int i = 0; i < 16; i++) acc[i] = 0.f;
        #pragma unroll 2
        for (int cc = 0; cc < 32; cc++) {
            float4 xv = *reinterpret_cast<const float4*>(&xs[j][cc * 4]);
            #pragma unroll
            for (int i = 0; i < 16; i++) {
                const float* Wrow = Wv + (g * 16 + i) * C_;
                float4 w = *reinterpret_cast<const float4*>(Wrow + cc * 4);
                acc[i] = fmaf(w.x, xv.x, fmaf(w.y, xv.y,
                         fmaf(w.z, xv.z, fmaf(w.w, xv.w, acc[i]))));
            }
        }
        #pragma unroll
        for (int i = 0; i < 16; i++) {
            int c = g * 16 + i;
            g_v[((size_t)b * C_ + c) * N_ + n0 + j] =
                __float2bfloat16_rn(acc[i] + bv[c]);
        }
    }
}

// ===========================================================================
// mma.sync flash attention — R14 structure at HALF the CTA size so 2 CTAs
// co-reside per SM (2 independent barrier domains phase-mix on the tensor
// pipe). 256 threads (8 warps), 128 queries/CTA, 64-key chunks, K/V
// double-buffered via cp.async. Warp w owns q rows [16w,16w+16). fp16 QK,
// bf16 PV; S/P in registers; O in 64 regs across all 128 chunks.
//
// SMEM: Q 128*144=18432 | KV buf x2 (K 9216 + V 18432 = 27648) = 55296
//   total 73728 (x2 CTAs = 147456 <= 228K). Epilogue reuses KV region.
// ===========================================================================
#define ROWB    144
#define SM_Q    0
#define SM_KV   18432
#define KVBUF   27648
#define OFF_K   0
#define OFF_V   9216
#define SM_TOTAL 73728
#define NCH     (N_ / 64)

__global__ __launch_bounds__(256, 2) void attn_kernel(
    const float* __restrict__ x, const float* __restrict__ gamma,
    float* __restrict__ out)
{
    extern __shared__ __align__(16) char smem[];
    const uint32_t sb = smem_u32(smem);

    const int b   = blockIdx.y;
    const int n0q = blockIdx.x * 128;
    const int t   = threadIdx.x;
    const int w   = t >> 5, l = t & 31;
    const int r8    = l & 7;
    const int half  = (l >> 3) & 1;
    const int quart = l >> 4;

    const __half*        k_b = g_k + (size_t)b * N_ * 64;
    const __nv_bfloat16* v_b = g_v + (size_t)b * C_ * N_;

    // ---- stage Q into padded smem rows (128 rows x 8 uint4) ----
    {
        const uint4* q = (const uint4*)(g_q + ((size_t)(b * N_ + n0q)) * 64);
        for (int i = t; i < 1024; i += 256) {
            int row = i >> 3, cs = i & 7;
            *(uint4*)(smem + SM_Q + row * ROWB + cs * 16) = q[i];
        }
    }

    // per-lane ldmatrix address components
    const uint32_t aRow  = (uint32_t)((w * 16 + half * 8 + r8) * ROWB); // A (Q rows)
    const uint32_t bRow  = (uint32_t)((quart * 8 + r8) * ROWB);         // B (K/V rows)
    const uint32_t aCol0 = (uint32_t)(quart * 16);                      // A col bytes
    const uint32_t bCol0 = (uint32_t)(half * 16);                       // B col bytes

    float o[16][4];
    #pragma unroll
    for (int i = 0; i < 16; i++)
        #pragma unroll
        for (int e = 0; e < 4; e++) o[i][e] = 0.f;
    float L0 = 0.f, L1 = 0.f;

    // ---- cp.async issue of one 64-key chunk into buffer bb (256 thr) ----
    auto issue = [&](int ch, int bb) {
        const int m0 = ch * 64;
        const uint32_t base = sb + SM_KV + bb * KVBUF;
        const int row = t >> 3, cs = t & 7;   // row 0..31
        // K: 64 rows
        CP_ASYNC16(base + OFF_K + row * ROWB + cs * 16,
                   k_b + (size_t)(m0 + row) * 64 + cs * 8);
        CP_ASYNC16(base + OFF_K + (row + 32) * ROWB + cs * 16,
                   k_b + (size_t)(m0 + row + 32) * 64 + cs * 8);
        // V: 128 channel-rows
        CP_ASYNC16(base + OFF_V + row * ROWB + cs * 16,
                   v_b + (size_t)row * N_ + m0 + cs * 8);
        CP_ASYNC16(base + OFF_V + (row + 32) * ROWB + cs * 16,
                   v_b + (size_t)(row + 32) * N_ + m0 + cs * 8);
        CP_ASYNC16(base + OFF_V + (row + 64) * ROWB + cs * 16,
                   v_b + (size_t)(row + 64) * N_ + m0 + cs * 8);
        CP_ASYNC16(base + OFF_V + (row + 96) * ROWB + cs * 16,
                   v_b + (size_t)(row + 96) * N_ + m0 + cs * 8);
    };

    issue(0, 0); CP_COMMIT();

    for (int ch = 0; ch < NCH; ch++) {
        const int bb = ch & 1;
        if (ch + 1 < NCH) { issue(ch + 1, bb ^ 1); CP_COMMIT(); CP_WAIT1(); }
        else              { CP_WAIT0(); }
        __syncthreads();

        const uint32_t kbase = sb + SM_KV + bb * KVBUF;

        // ---- QK (fp16 single product, K=48: 3 k16 steps) ----
        float s[8][4];
        #pragma unroll
        for (int i = 0; i < 8; i++)
            #pragma unroll
            for (int e = 0; e < 4; e++) s[i][e] = 0.f;

        #pragma unroll
        for (int ks = 0; ks < 3; ks++) {
            uint32_t qa0, qa1, qa2, qa3;
            LDSM_X4(qa0, qa1, qa2, qa3, sb + SM_Q + aRow + aCol0 + ks * 32);
            #pragma unroll
            for (int np = 0; np < 4; np++) {
                uint32_t k0, k1, k2, k3;
                LDSM_X4(k0, k1, k2, k3,
                        kbase + OFF_K + np * (16 * ROWB) + bRow + bCol0 + ks * 32);
                MMA_F16(s[2*np],     qa0, qa1, qa2, qa3, k0, k1);
                MMA_F16(s[2*np + 1], qa0, qa1, qa2, qa3, k2, k3);
            }
        }

        // ---- fixed-bias softmax: p = exp2(s - 64); repack S-frags -> A-frags ----
        uint32_t pa[4][4];
        float rs0 = 0.f, rs1 = 0.f;
        #pragma unroll
        for (int nt = 0; nt < 8; nt++) {
            float p0 = ex2f(s[nt][0] - BIAS2);
            float p1 = ex2f(s[nt][1] - BIAS2);
            float p2 = ex2f(s[nt][2] - BIAS2);
            float p3 = ex2f(s[nt][3] - BIAS2);
            rs0 += p0 + p1;
            rs1 += p2 + p3;
            int kk = nt >> 1;
            if ((nt & 1) == 0) { pa[kk][0] = packbf2(p0, p1); pa[kk][1] = packbf2(p2, p3); }
            else               { pa[kk][2] = packbf2(p0, p1); pa[kk][3] = packbf2(p2, p3); }
        }
        rs0 += __shfl_xor_sync(0xffffffffu, rs0, 1);
        rs0 += __shfl_xor_sync(0xffffffffu, rs0, 2);
        rs1 += __shfl_xor_sync(0xffffffffu, rs1, 1);
        rs1 += __shfl_xor_sync(0xffffffffu, rs1, 2);
        L0 += rs0;
        L1 += rs1;

        // ---- PV: O += P.V  (bf16, K=64: 4 k16 steps, 16 channel tiles) ----
        #pragma unroll
        for (int kk = 0; kk < 4; kk++) {
            #pragma unroll
            for (int cp = 0; cp < 8; cp++) {
                uint32_t v0, v1, v2, v3;
                LDSM_X4(v0, v1, v2, v3,
                        kbase + OFF_V + cp * (16 * ROWB) + bRow + bCol0 + kk * 32);
                MMA_BF16(o[2*cp],     pa[kk][0], pa[kk][1], pa[kk][2], pa[kk][3], v0, v1);
                MMA_BF16(o[2*cp + 1], pa[kk][0], pa[kk][1], pa[kk][2], pa[kk][3], v2, v3);
            }
        }
        __syncthreads();   // all warps done with buf bb before it is refilled
    }

    // ---- epilogue: out = gamma * O / L + x  (per-warp smem transpose) ----
    const float gm  = __ldg(gamma);
    const float sc0 = gm / L0;
    const float sc1 = gm / L1;
    const int   g   = l >> 2, t4 = l & 3;

    float* buf = (float*)(smem + SM_KV);   // [128][9] floats, KV region dead
    #pragma unroll 1
    for (int ct = 0; ct < 16; ct++) {
        __syncthreads();
        {
            int q0 = w * 16 + g;
            buf[q0 * 9 + 2*t4]           = o[ct][0] * sc0;
            buf[q0 * 9 + 2*t4 + 1]       = o[ct][1] * sc0;
            buf[(q0 + 8) * 9 + 2*t4]     = o[ct][2] * sc1;
            buf[(q0 + 8) * 9 + 2*t4 + 1] = o[ct][3] * sc1;
        }
        __syncthreads();
        for (int i = t; i < 1024; i += 256) {
            int cl = i >> 7, q = i & 127;
            int c  = ct * 8 + cl;
            size_t go = ((size_t)b * C_ + c) * N_ + n0q + q;
            out[go] = buf[q * 9 + cl] + x[go];
        }
    }
}

// ===========================================================================
extern "C" void kernel_launch(void* const* d_in, const int* in_sizes, int n_in,
                              void* d_out, int out_size)
{
    (void)in_sizes; (void)n_in; (void)out_size;
    const float* x     = (const float*)d_in[0];
    const float* xyz   = (const float*)d_in[1];
    const float* Wq    = (const float*)d_in[2];
    const float* bq    = (const float*)d_in[3];
    const float* Wk    = (const float*)d_in[4];
    const float* bk    = (const float*)d_in[5];
    const float* Wv    = (const float*)d_in[6];
    const float* bv    = (const float*)d_in[7];
    const float* gamma = (const float*)d_in[8];
    float* out = (float*)d_out;

    cudaFuncSetAttribute(attn_kernel,
                         cudaFuncAttributeMaxDynamicSharedMemorySize, SM_TOTAL);

    dim3 pg(N_ / 32, B_);
    proj_kernel<<<pg, 256>>>(x, xyz, Wq, bq, Wk, bk, Wv, bv);

    dim3 ag(N_ / 128, B_);
    attn_kernel<<<ag, 256, SM_TOTAL>>>(x, gamma, out);
}